// round 1
// baseline (speedup 1.0000x reference)
#include <cuda_runtime.h>
#include <cstdint>

#define NN     100000
#define EE     1600000
#define DIN    256
#define DOUT   64
#define ALPHA  0.2f

#define G_ROWS 128
#define G_KC   32
#define MMBLOCKS 1024

// ---------------- scratch (static device allocations are allowed) ----------
__device__ float d_Xp[(size_t)NN * DOUT];      // 25.6 MB  X @ W
__device__ float d_s0[NN];
__device__ float d_s1[NN];
__device__ float d_att[EE];                    // 6.4 MB   edge attention
__device__ int   d_rowptr[NN + 1];
__device__ float d_bmin[MMBLOCKS];
__device__ float d_bmax[MMBLOCKS];
__device__ float d_mn;
__device__ float d_scale;

// ---------------- 1) GEMM: X[N,256] @ W[256,64] -> d_Xp[N,64] --------------
// 128 rows x 64 cols per block, 256 threads, 8x4 register tile per thread.
__global__ void __launch_bounds__(256) gemm_kernel(const float* __restrict__ X,
                                                   const float* __restrict__ W,
                                                   int nrows) {
    __shared__ float Xs[G_KC][G_ROWS + 1];   // transposed, padded: conflict-free
    __shared__ float Wsh[G_KC][DOUT];

    const int t  = threadIdx.x;
    const int tx = t & 15;       // col group: cols [tx*4, tx*4+4)
    const int ty = t >> 4;       // row group base
    const int row0 = blockIdx.x * G_ROWS;

    float acc[8][4];
#pragma unroll
    for (int i = 0; i < 8; i++)
#pragma unroll
        for (int j = 0; j < 4; j++) acc[i][j] = 0.f;

    for (int k0 = 0; k0 < DIN; k0 += G_KC) {
        // load X tile (128 rows x 32 k), stored transposed
#pragma unroll
        for (int j = 0; j < 4; j++) {
            int p  = t + j * 256;     // 0..1023 float4 slots
            int r  = p >> 3;          // 0..127
            int kq = p & 7;           // 0..7 (float4 along k)
            float4 v = make_float4(0.f, 0.f, 0.f, 0.f);
            int gr = row0 + r;
            if (gr < nrows)
                v = *(const float4*)&X[(size_t)gr * DIN + k0 + kq * 4];
            Xs[kq * 4 + 0][r] = v.x;
            Xs[kq * 4 + 1][r] = v.y;
            Xs[kq * 4 + 2][r] = v.z;
            Xs[kq * 4 + 3][r] = v.w;
        }
        // load W tile (32 k x 64 cols)
#pragma unroll
        for (int j = 0; j < 2; j++) {
            int p  = t + j * 256;     // 0..511 float4 slots
            int kk = p >> 4;          // 0..31
            int c4 = p & 15;          // 0..15
            *(float4*)&Wsh[kk][c4 * 4] =
                *(const float4*)&W[(size_t)(k0 + kk) * DOUT + c4 * 4];
        }
        __syncthreads();

#pragma unroll
        for (int k = 0; k < G_KC; k++) {
            float4 wv = *(const float4*)&Wsh[k][tx * 4];
#pragma unroll
            for (int i = 0; i < 8; i++) {
                float xv = Xs[k][ty + i * 16];
                acc[i][0] += xv * wv.x;
                acc[i][1] += xv * wv.y;
                acc[i][2] += xv * wv.z;
                acc[i][3] += xv * wv.w;
            }
        }
        __syncthreads();
    }

#pragma unroll
    for (int i = 0; i < 8; i++) {
        int gr = row0 + ty + i * 16;
        if (gr < nrows) {
            float4 o = make_float4(acc[i][0], acc[i][1], acc[i][2], acc[i][3]);
            *(float4*)&d_Xp[(size_t)gr * DOUT + tx * 4] = o;
        }
    }
}

// ---------------- 2) per-node scores: s0 = Xp . a0, s1 = Xp . a1 -----------
__global__ void __launch_bounds__(256) score_kernel(const float* __restrict__ a0,
                                                    const float* __restrict__ a1,
                                                    int nrows) {
    int gid  = blockIdx.x * blockDim.x + threadIdx.x;
    int row  = gid >> 5;
    int lane = gid & 31;
    if (row >= nrows) return;
    float2 x  = *(const float2*)&d_Xp[(size_t)row * DOUT + lane * 2];
    float2 b0 = *(const float2*)&a0[lane * 2];
    float2 b1 = *(const float2*)&a1[lane * 2];
    float p0 = x.x * b0.x + x.y * b0.y;
    float p1 = x.x * b1.x + x.y * b1.y;
#pragma unroll
    for (int o = 16; o; o >>= 1) {
        p0 += __shfl_down_sync(0xFFFFFFFFu, p0, o);
        p1 += __shfl_down_sync(0xFFFFFFFFu, p1, o);
    }
    if (lane == 0) {
        d_s0[row] = p0;
        d_s1[row] = p1;
    }
}

// ---------------- 3) row_ptr from sorted row_index (binary search) ---------
__global__ void rowptr_kernel(const int* __restrict__ ri, int nrows, int ne) {
    int r = blockIdx.x * blockDim.x + threadIdx.x;
    if (r > nrows) return;
    int lo = 0, hi = ne;
    while (lo < hi) {
        int mid = (lo + hi) >> 1;
        if (ri[mid] < r) lo = mid + 1; else hi = mid;
    }
    d_rowptr[r] = lo;
}

// ---------------- 4) SDDMM + LeakyReLU + per-block min/max -----------------
__global__ void __launch_bounds__(256) edge_kernel(const int* __restrict__ ri,
                                                   const int* __restrict__ ci,
                                                   int ne) {
    float lmin = 3.4e38f, lmax = -3.4e38f;
    for (int e = blockIdx.x * blockDim.x + threadIdx.x; e < ne;
         e += gridDim.x * blockDim.x) {
        float v = d_s0[ri[e]] + d_s1[ci[e]];
        v = v > 0.f ? v : ALPHA * v;
        d_att[e] = v;
        lmin = fminf(lmin, v);
        lmax = fmaxf(lmax, v);
    }
    __shared__ float smn[256], smx[256];
    int t = threadIdx.x;
    smn[t] = lmin; smx[t] = lmax;
    __syncthreads();
#pragma unroll
    for (int s = 128; s; s >>= 1) {
        if (t < s) {
            smn[t] = fminf(smn[t], smn[t + s]);
            smx[t] = fmaxf(smx[t], smx[t + s]);
        }
        __syncthreads();
    }
    if (t == 0) {
        d_bmin[blockIdx.x] = smn[0];
        d_bmax[blockIdx.x] = smx[0];
    }
}

// ---------------- 5) finalize global min / scale ---------------------------
__global__ void minmax_kernel() {
    __shared__ float smn[MMBLOCKS], smx[MMBLOCKS];
    int t = threadIdx.x;
    smn[t] = d_bmin[t];
    smx[t] = d_bmax[t];
    __syncthreads();
#pragma unroll
    for (int s = MMBLOCKS / 2; s; s >>= 1) {
        if (t < s) {
            smn[t] = fminf(smn[t], smn[t + s]);
            smx[t] = fmaxf(smx[t], smx[t + s]);
        }
        __syncthreads();
    }
    if (t == 0) {
        float mn = smn[0], mx = smx[0];
        d_mn = mn;
        d_scale = 1.0f / (mx - mn);
    }
}

// ---------------- 6) att = exp((att - mn) * scale) -------------------------
__global__ void __launch_bounds__(256) expmap_kernel(int ne4) {
    int i = blockIdx.x * blockDim.x + threadIdx.x;
    if (i >= ne4) return;
    float mn = d_mn, sc = d_scale;
    float4 v = *(float4*)&d_att[(size_t)i * 4];
    v.x = __expf((v.x - mn) * sc);
    v.y = __expf((v.y - mn) * sc);
    v.z = __expf((v.z - mn) * sc);
    v.w = __expf((v.w - mn) * sc);
    *(float4*)&d_att[(size_t)i * 4] = v;
}

// ---------------- 7) SpMM + row normalization (warp per row) ---------------
__global__ void __launch_bounds__(256) spmm_kernel(const int* __restrict__ ci,
                                                   float* __restrict__ out,
                                                   int nrows) {
    int gid  = blockIdx.x * blockDim.x + threadIdx.x;
    int r    = gid >> 5;
    int lane = gid & 31;
    if (r >= nrows) return;

    int e   = d_rowptr[r];
    int end = d_rowptr[r + 1];
    const int off = lane * 2;

    float ax = 0.f, ay = 0.f, s = 0.f;
    for (; e + 1 < end; e += 2) {
        int   c0 = ci[e],       c1 = ci[e + 1];
        float a0 = d_att[e],    a1 = d_att[e + 1];
        float2 x0 = *(const float2*)&d_Xp[(size_t)c0 * DOUT + off];
        float2 x1 = *(const float2*)&d_Xp[(size_t)c1 * DOUT + off];
        s  += a0 + a1;
        ax += a0 * x0.x + a1 * x1.x;
        ay += a0 * x0.y + a1 * x1.y;
    }
    if (e < end) {
        int   c0 = ci[e];
        float a0 = d_att[e];
        float2 x0 = *(const float2*)&d_Xp[(size_t)c0 * DOUT + off];
        s  += a0;
        ax += a0 * x0.x;
        ay += a0 * x0.y;
    }
    float inv = 1.0f / fmaxf(s, 1e-12f);
    float2 o = make_float2(ax * inv, ay * inv);
    *(float2*)&out[(size_t)r * DOUT + off] = o;
}

// ---------------- launch ---------------------------------------------------
extern "C" void kernel_launch(void* const* d_in, const int* in_sizes, int n_in,
                              void* d_out, int out_size) {
    const float* X  = (const float*)d_in[0];
    const float* W  = (const float*)d_in[1];
    const float* a0 = (const float*)d_in[2];
    const float* a1 = (const float*)d_in[3];
    const int*   ri = (const int*)d_in[4];
    const int*   ci = (const int*)d_in[5];
    float*       out = (float*)d_out;

    const int n = out_size / DOUT;   // 100000
    const int e = in_sizes[4];       // 1600000

    gemm_kernel<<<(n + G_ROWS - 1) / G_ROWS, 256>>>(X, W, n);
    score_kernel<<<(n * 32 + 255) / 256, 256>>>(a0, a1, n);
    rowptr_kernel<<<(n + 1 + 255) / 256, 256>>>(ri, n, e);
    edge_kernel<<<MMBLOCKS, 256>>>(ri, ci, e);
    minmax_kernel<<<1, MMBLOCKS>>>();
    expmap_kernel<<<(e / 4 + 255) / 256, 256>>>(e / 4);
    spmm_kernel<<<(n * 32 + 255) / 256, 256>>>(ci, out, n);
}

// round 4
// speedup vs baseline: 1.1703x; 1.1703x over previous
#include <cuda_runtime.h>
#include <cstdint>

#define NN     100000
#define EE     1600000
#define DIN    256
#define DOUT   64
#define ALPHA  0.2f
#define MMBLOCKS 1024

// ---------------- scratch ---------------------------------------------------
__device__ float d_Xp[(size_t)NN * DOUT];      // 25.6 MB  X @ W
__device__ float d_s0[NN];
__device__ float d_s1[NN];
__device__ float d_att[EE];                    // leakyrelu'd scores (pre-exp)
__device__ int   d_rowptr[NN + 1];
__device__ float d_bmin[MMBLOCKS];
__device__ float d_bmax[MMBLOCKS];
__device__ float d_mn;
__device__ float d_scale;

// ---------------- tf32 helpers ----------------------------------------------
__device__ __forceinline__ float tf32_hi(float v) {
    return __uint_as_float(__float_as_uint(v) & 0xFFFFE000u);
}

// mma.sync m16n8k8 tf32: D += A * B  (A row-major 16x8, B col-major 8x8)
__device__ __forceinline__ void mma_tf32(float* d,
                                         uint32_t a0, uint32_t a1,
                                         uint32_t a2, uint32_t a3,
                                         uint32_t b0, uint32_t b1) {
    asm volatile(
        "mma.sync.aligned.m16n8k8.row.col.f32.tf32.tf32.f32 "
        "{%0,%1,%2,%3}, {%4,%5,%6,%7}, {%8,%9}, {%0,%1,%2,%3};"
        : "+f"(d[0]), "+f"(d[1]), "+f"(d[2]), "+f"(d[3])
        : "r"(a0), "r"(a1), "r"(a2), "r"(a3), "r"(b0), "r"(b1));
}

// ---------------- 1) tensor-core GEMM: X[N,256] @ W[256,64] -----------------
// CTA: 256 threads, 8 warps, 256 rows. Warp w: rows [w*32, w*32+32), cols 0..64.
// K processed in 4 chunks of 64; W chunk transposed in smem [64 n][68] (padded).
// 3xTF32 passes (hi*hi + hi*lo + lo*hi) for fp32-grade accuracy.
#define KC       64    // k-chunk width
#define GW_STRIDE 68   // 68 % 32 == 4 -> B-frag lds is bank-conflict-free

__global__ void __launch_bounds__(256, 2)
gemm_mma_kernel(const float* __restrict__ X, const float* __restrict__ W,
                int nrows) {
    __shared__ float Bh[DOUT * GW_STRIDE];   // W^T hi chunk (17.4 KB)
    __shared__ float Bl[DOUT * GW_STRIDE];   // W^T lo chunk (17.4 KB)

    const int tid  = threadIdx.x;
    const int wid  = tid >> 5;
    const int lane = tid & 31;
    const int g    = lane >> 2;   // group id  (0..7)
    const int t    = lane & 3;    // thread-in-group (0..3)

    const int m0 = blockIdx.x * 256 + wid * 32;
    const int r0 = m0 + g, r1 = m0 + g + 8, r2 = m0 + g + 16, r3 = m0 + g + 24;
    const bool v0 = r0 < nrows, v1 = r1 < nrows, v2 = r2 < nrows, v3 = r3 < nrows;
    const float* x0 = X + (size_t)r0 * DIN;
    const float* x1 = X + (size_t)r1 * DIN;
    const float* x2 = X + (size_t)r2 * DIN;
    const float* x3 = X + (size_t)r3 * DIN;

    float acc[2][8][4];
#pragma unroll
    for (int mt = 0; mt < 2; mt++)
#pragma unroll
        for (int nt = 0; nt < 8; nt++)
#pragma unroll
            for (int q = 0; q < 4; q++) acc[mt][nt][q] = 0.f;

#pragma unroll 1
    for (int kc = 0; kc < DIN / KC; kc++) {
        // ---- load W chunk transposed, hi/lo split ----
        if (kc) __syncthreads();               // previous chunk fully consumed
        for (int idx = tid; idx < DOUT * KC; idx += 256) {
            int n = idx & 63, kk = idx >> 6;   // kk in [0,64)
            float v = W[(size_t)(kc * KC + kk) * DOUT + n];
            float h = tf32_hi(v);
            Bh[n * GW_STRIDE + kk] = h;
            Bl[n * GW_STRIDE + kk] = v - h;
        }
        __syncthreads();

        const int kbase = kc * KC;
#pragma unroll
        for (int k0 = 0; k0 < KC; k0 += 8) {
            const int ks = kbase + k0;
            // A fragments from gmem (each element read once per CTA)
            float a00 = v0 ? x0[ks + t]     : 0.f;
            float a01 = v1 ? x1[ks + t]     : 0.f;
            float a02 = v0 ? x0[ks + t + 4] : 0.f;
            float a03 = v1 ? x1[ks + t + 4] : 0.f;
            float a10 = v2 ? x2[ks + t]     : 0.f;
            float a11 = v3 ? x3[ks + t]     : 0.f;
            float a12 = v2 ? x2[ks + t + 4] : 0.f;
            float a13 = v3 ? x3[ks + t + 4] : 0.f;

            uint32_t ah[2][4], al[2][4];
            {
                float h;
                h = tf32_hi(a00); ah[0][0] = __float_as_uint(h); al[0][0] = __float_as_uint(a00 - h);
                h = tf32_hi(a01); ah[0][1] = __float_as_uint(h); al[0][1] = __float_as_uint(a01 - h);
                h = tf32_hi(a02); ah[0][2] = __float_as_uint(h); al[0][2] = __float_as_uint(a02 - h);
                h = tf32_hi(a03); ah[0][3] = __float_as_uint(h); al[0][3] = __float_as_uint(a03 - h);
                h = tf32_hi(a10); ah[1][0] = __float_as_uint(h); al[1][0] = __float_as_uint(a10 - h);
                h = tf32_hi(a11); ah[1][1] = __float_as_uint(h); al[1][1] = __float_as_uint(a11 - h);
                h = tf32_hi(a12); ah[1][2] = __float_as_uint(h); al[1][2] = __float_as_uint(a12 - h);
                h = tf32_hi(a13); ah[1][3] = __float_as_uint(h); al[1][3] = __float_as_uint(a13 - h);
            }

#pragma unroll
            for (int nt = 0; nt < 8; nt++) {
                const float* bhp = &Bh[(nt * 8 + g) * GW_STRIDE + k0 + t];
                const float* blp = &Bl[(nt * 8 + g) * GW_STRIDE + k0 + t];
                uint32_t bh0 = __float_as_uint(bhp[0]);
                uint32_t bh1 = __float_as_uint(bhp[4]);
                uint32_t bl0 = __float_as_uint(blp[0]);
                uint32_t bl1 = __float_as_uint(blp[4]);
#pragma unroll
                for (int mt = 0; mt < 2; mt++) {
                    mma_tf32(acc[mt][nt], ah[mt][0], ah[mt][1], ah[mt][2], ah[mt][3], bh0, bh1);
                    mma_tf32(acc[mt][nt], ah[mt][0], ah[mt][1], ah[mt][2], ah[mt][3], bl0, bl1);
                    mma_tf32(acc[mt][nt], al[mt][0], al[mt][1], al[mt][2], al[mt][3], bh0, bh1);
                }
            }
        }
    }

    // epilogue: c0 -> (g, 2t), c1 -> (g, 2t+1), c2 -> (g+8, 2t), c3 -> (g+8, 2t+1)
#pragma unroll
    for (int mt = 0; mt < 2; mt++) {
        int rowA = m0 + mt * 16 + g;
        int rowB = rowA + 8;
#pragma unroll
        for (int nt = 0; nt < 8; nt++) {
            int col = nt * 8 + t * 2;
            if (rowA < nrows)
                *(float2*)&d_Xp[(size_t)rowA * DOUT + col] =
                    make_float2(acc[mt][nt][0], acc[mt][nt][1]);
            if (rowB < nrows)
                *(float2*)&d_Xp[(size_t)rowB * DOUT + col] =
                    make_float2(acc[mt][nt][2], acc[mt][nt][3]);
        }
    }
}

// ---------------- 2) per-node scores ---------------------------------------
__global__ void __launch_bounds__(256) score_kernel(const float* __restrict__ a0,
                                                    const float* __restrict__ a1,
                                                    int nrows) {
    int gid  = blockIdx.x * blockDim.x + threadIdx.x;
    int row  = gid >> 5;
    int lane = gid & 31;
    if (row >= nrows) return;
    float2 x  = *(const float2*)&d_Xp[(size_t)row * DOUT + lane * 2];
    float2 b0 = *(const float2*)&a0[lane * 2];
    float2 b1 = *(const float2*)&a1[lane * 2];
    float p0 = x.x * b0.x + x.y * b0.y;
    float p1 = x.x * b1.x + x.y * b1.y;
#pragma unroll
    for (int o = 16; o; o >>= 1) {
        p0 += __shfl_down_sync(0xFFFFFFFFu, p0, o);
        p1 += __shfl_down_sync(0xFFFFFFFFu, p1, o);
    }
    if (lane == 0) {
        d_s0[row] = p0;
        d_s1[row] = p1;
    }
}

// ---------------- 3) row_ptr from sorted row_index --------------------------
__global__ void rowptr_kernel(const int* __restrict__ ri, int nrows, int ne) {
    int r = blockIdx.x * blockDim.x + threadIdx.x;
    if (r > nrows) return;
    int lo = 0, hi = ne;
    while (lo < hi) {
        int mid = (lo + hi) >> 1;
        if (ri[mid] < r) lo = mid + 1; else hi = mid;
    }
    d_rowptr[r] = lo;
}

// ---------------- 4) SDDMM + LeakyReLU + per-block min/max (4 edges/thread) -
__global__ void __launch_bounds__(256) edge_kernel(const int* __restrict__ ri,
                                                   const int* __restrict__ ci,
                                                   int ne) {
    float lmin = 3.4e38f, lmax = -3.4e38f;
    int ne4 = ne >> 2;
    for (int i = blockIdx.x * blockDim.x + threadIdx.x; i < ne4;
         i += gridDim.x * blockDim.x) {
        int4 r4 = *(const int4*)&ri[(size_t)i * 4];
        int4 c4 = *(const int4*)&ci[(size_t)i * 4];
        float v0 = d_s0[r4.x] + d_s1[c4.x];
        float v1 = d_s0[r4.y] + d_s1[c4.y];
        float v2 = d_s0[r4.z] + d_s1[c4.z];
        float v3 = d_s0[r4.w] + d_s1[c4.w];
        v0 = v0 > 0.f ? v0 : ALPHA * v0;
        v1 = v1 > 0.f ? v1 : ALPHA * v1;
        v2 = v2 > 0.f ? v2 : ALPHA * v2;
        v3 = v3 > 0.f ? v3 : ALPHA * v3;
        *(float4*)&d_att[(size_t)i * 4] = make_float4(v0, v1, v2, v3);
        lmin = fminf(lmin, fminf(fminf(v0, v1), fminf(v2, v3)));
        lmax = fmaxf(lmax, fmaxf(fmaxf(v0, v1), fmaxf(v2, v3)));
    }
    // scalar tail (ne not divisible by 4)
    int gid = blockIdx.x * blockDim.x + threadIdx.x;
    int tail0 = ne4 * 4;
    if (gid < ne - tail0) {
        int e = tail0 + gid;
        float v = d_s0[ri[e]] + d_s1[ci[e]];
        v = v > 0.f ? v : ALPHA * v;
        d_att[e] = v;
        lmin = fminf(lmin, v);
        lmax = fmaxf(lmax, v);
    }
    __shared__ float smn[256], smx[256];
    int t = threadIdx.x;
    smn[t] = lmin; smx[t] = lmax;
    __syncthreads();
#pragma unroll
    for (int s = 128; s; s >>= 1) {
        if (t < s) {
            smn[t] = fminf(smn[t], smn[t + s]);
            smx[t] = fmaxf(smx[t], smx[t + s]);
        }
        __syncthreads();
    }
    if (t == 0) {
        d_bmin[blockIdx.x] = smn[0];
        d_bmax[blockIdx.x] = smx[0];
    }
}

// ---------------- 5) finalize global min / scale ---------------------------
__global__ void minmax_kernel() {
    __shared__ float smn[MMBLOCKS], smx[MMBLOCKS];
    int t = threadIdx.x;
    smn[t] = d_bmin[t];
    smx[t] = d_bmax[t];
    __syncthreads();
#pragma unroll
    for (int s = MMBLOCKS / 2; s; s >>= 1) {
        if (t < s) {
            smn[t] = fminf(smn[t], smn[t + s]);
            smx[t] = fmaxf(smx[t], smx[t + s]);
        }
        __syncthreads();
    }
    if (t == 0) {
        float mn = smn[0], mx = smx[0];
        d_mn = mn;
        d_scale = 1.0f / (mx - mn);
    }
}

// ---------------- 6) SpMM + exp + row normalization (warp per row) ---------
__global__ void __launch_bounds__(256) spmm_kernel(const int* __restrict__ ci,
                                                   float* __restrict__ out,
                                                   int nrows) {
    int gid  = blockIdx.x * blockDim.x + threadIdx.x;
    int r    = gid >> 5;
    int lane = gid & 31;
    if (r >= nrows) return;

    const float mn = d_mn, sc = d_scale;
    int e   = d_rowptr[r];
    int end = d_rowptr[r + 1];
    const int off = lane * 2;

    float ax = 0.f, ay = 0.f, s = 0.f;
    for (; e + 1 < end; e += 2) {
        int   c0 = ci[e],    c1 = ci[e + 1];
        float a0 = __expf((d_att[e]     - mn) * sc);
        float a1 = __expf((d_att[e + 1] - mn) * sc);
        float2 x0 = *(const float2*)&d_Xp[(size_t)c0 * DOUT + off];
        float2 x1 = *(const float2*)&d_Xp[(size_t)c1 * DOUT + off];
        s  += a0 + a1;
        ax += a0 * x0.x + a1 * x1.x;
        ay += a0 * x0.y + a1 * x1.y;
    }
    if (e < end) {
        int   c0 = ci[e];
        float a0 = __expf((d_att[e] - mn) * sc);
        float2 x0 = *(const float2*)&d_Xp[(size_t)c0 * DOUT + off];
        s  += a0;
        ax += a0 * x0.x;
        ay += a0 * x0.y;
    }
    float inv = 1.0f / fmaxf(s, 1e-12f);
    *(float2*)&out[(size_t)r * DOUT + off] = make_float2(ax * inv, ay * inv);
}

// ---------------- launch ---------------------------------------------------
extern "C" void kernel_launch(void* const* d_in, const int* in_sizes, int n_in,
                              void* d_out, int out_size) {
    const float* X  = (const float*)d_in[0];
    const float* W  = (const float*)d_in[1];
    const float* a0 = (const float*)d_in[2];
    const float* a1 = (const float*)d_in[3];
    const int*   ri = (const int*)d_in[4];
    const int*   ci = (const int*)d_in[5];
    float*       out = (float*)d_out;

    const int n = out_size / DOUT;   // 100000
    const int e = in_sizes[4];       // 1600000

    gemm_mma_kernel<<<(n + 255) / 256, 256>>>(X, W, n);
    score_kernel<<<(n * 32 + 255) / 256, 256>>>(a0, a1, n);
    rowptr_kernel<<<(n + 1 + 255) / 256, 256>>>(ri, n, e);
    edge_kernel<<<MMBLOCKS, 256>>>(ri, ci, e);
    minmax_kernel<<<1, MMBLOCKS>>>();
    spmm_kernel<<<(n * 32 + 255) / 256, 256>>>(ci, out, n);
}

// round 5
// speedup vs baseline: 1.4998x; 1.2815x over previous
#include <cuda_runtime.h>
#include <cuda_bf16.h>
#include <cstdint>

#define NN     100000
#define EE     1600000
#define DIN    256
#define DOUT   64
#define ALPHA  0.2f
#define MMBLOCKS 1024

// ---------------- scratch ---------------------------------------------------
__device__ float d_Xp[(size_t)NN * DOUT];      // 25.6 MB  X @ W
__device__ float d_s0[NN];
__device__ float d_s1[NN];
__device__ float d_att[EE];                    // leakyrelu'd scores (pre-exp)
__device__ int   d_rowptr[NN + 1];
__device__ float d_bmin[MMBLOCKS];
__device__ float d_bmax[MMBLOCKS];
__device__ float d_mn;
__device__ float d_scale;

// ---------------- bf16 helpers ----------------------------------------------
__device__ __forceinline__ uint32_t pack_bf16(float a, float b) {
    __nv_bfloat162 h = __floats2bfloat162_rn(a, b);   // a -> low half
    return *(uint32_t*)&h;
}
// split v into hi (bf16) + lo (bf16 of remainder); returns as floats
__device__ __forceinline__ void bsplit(float v, float& h, float& l) {
    h = __bfloat162float(__float2bfloat16_rn(v));
    l = v - h;
}

// mma.sync m16n8k16 bf16: D += A * B (A row-major 16x16, B col-major 16x8)
__device__ __forceinline__ void mma_bf16(float* d,
                                         uint32_t a0, uint32_t a1,
                                         uint32_t a2, uint32_t a3,
                                         uint32_t b0, uint32_t b1) {
    asm volatile(
        "mma.sync.aligned.m16n8k16.row.col.f32.bf16.bf16.f32 "
        "{%0,%1,%2,%3}, {%4,%5,%6,%7}, {%8,%9}, {%0,%1,%2,%3};"
        : "+f"(d[0]), "+f"(d[1]), "+f"(d[2]), "+f"(d[3])
        : "r"(a0), "r"(a1), "r"(a2), "r"(a3), "r"(b0), "r"(b1));
}

// ---------------- 1) bf16-split tensor GEMM + fused scores ------------------
// CTA: 256 threads / 8 warps / 256 rows. Warp w: rows [w*32, w*32+32), all 64 cols.
// K in 4 chunks of 64; W chunk in smem as packed bf16x2 (hi & lo), stride 36
// words -> B-fragment LDS bank-conflict-free (bank = 4g + t).
// 3 passes (hi*hi + hi*lo + lo*hi) => ~1e-5 accuracy on Xp.
#define KC        64
#define BSTRIDE   36   // uint32 words per n-col (32 kpairs + pad)

__global__ void __launch_bounds__(256, 2)
gemm_mma_kernel(const float* __restrict__ X, const float* __restrict__ W,
                const float* __restrict__ va0, const float* __restrict__ va1,
                int nrows) {
    __shared__ uint32_t Bh[DOUT * BSTRIDE];   // 9.2 KB  W^T hi (bf16x2)
    __shared__ uint32_t Bl[DOUT * BSTRIDE];   // 9.2 KB  W^T lo

    const int tid  = threadIdx.x;
    const int wid  = tid >> 5;
    const int lane = tid & 31;
    const int g    = lane >> 2;   // 0..7
    const int t    = lane & 3;    // 0..3

    const int m0 = blockIdx.x * 256 + wid * 32;
    const int r0 = m0 + g, r1 = m0 + g + 8, r2 = m0 + g + 16, r3 = m0 + g + 24;
    const bool v0 = r0 < nrows, v1 = r1 < nrows, v2 = r2 < nrows, v3 = r3 < nrows;
    const float* x0 = X + (size_t)r0 * DIN;
    const float* x1 = X + (size_t)r1 * DIN;
    const float* x2 = X + (size_t)r2 * DIN;
    const float* x3 = X + (size_t)r3 * DIN;

    float acc[2][8][4];
#pragma unroll
    for (int mt = 0; mt < 2; mt++)
#pragma unroll
        for (int nt = 0; nt < 8; nt++)
#pragma unroll
            for (int q = 0; q < 4; q++) acc[mt][nt][q] = 0.f;

#pragma unroll 1
    for (int kc = 0; kc < DIN / KC; kc++) {
        if (kc) __syncthreads();
        // fill W chunk: 64 n-cols x 32 kpairs
        for (int idx = tid; idx < DOUT * (KC / 2); idx += 256) {
            int n  = idx & 63;
            int kp = idx >> 6;                 // 0..31
            int k  = kc * KC + kp * 2;
            float w0 = W[(size_t)k * DOUT + n];
            float w1 = W[(size_t)(k + 1) * DOUT + n];
            float h0, l0, h1, l1;
            bsplit(w0, h0, l0);
            bsplit(w1, h1, l1);
            Bh[n * BSTRIDE + kp] = pack_bf16(h0, h1);
            Bl[n * BSTRIDE + kp] = pack_bf16(l0, l1);
        }
        __syncthreads();

#pragma unroll
        for (int s = 0; s < KC / 16; s++) {        // 16-k steps
            const int ks  = kc * KC + s * 16;
            const int kp0 = s * 8;                 // kpair base in chunk

            // A fragments: rows {g,g+8,g+16,g+24}, cols {2t,2t+1, 2t+8,2t+9}
            float2 fa0 = v0 ? *(const float2*)(x0 + ks + 2 * t)     : make_float2(0.f, 0.f);
            float2 fa2 = v0 ? *(const float2*)(x0 + ks + 2 * t + 8) : make_float2(0.f, 0.f);
            float2 fb0 = v1 ? *(const float2*)(x1 + ks + 2 * t)     : make_float2(0.f, 0.f);
            float2 fb2 = v1 ? *(const float2*)(x1 + ks + 2 * t + 8) : make_float2(0.f, 0.f);
            float2 fc0 = v2 ? *(const float2*)(x2 + ks + 2 * t)     : make_float2(0.f, 0.f);
            float2 fc2 = v2 ? *(const float2*)(x2 + ks + 2 * t + 8) : make_float2(0.f, 0.f);
            float2 fd0 = v3 ? *(const float2*)(x3 + ks + 2 * t)     : make_float2(0.f, 0.f);
            float2 fd2 = v3 ? *(const float2*)(x3 + ks + 2 * t + 8) : make_float2(0.f, 0.f);

            uint32_t ah[2][4], al[2][4];
            {
                float hx, lx, hy, ly;
                bsplit(fa0.x, hx, lx); bsplit(fa0.y, hy, ly);
                ah[0][0] = pack_bf16(hx, hy); al[0][0] = pack_bf16(lx, ly);
                bsplit(fb0.x, hx, lx); bsplit(fb0.y, hy, ly);
                ah[0][1] = pack_bf16(hx, hy); al[0][1] = pack_bf16(lx, ly);
                bsplit(fa2.x, hx, lx); bsplit(fa2.y, hy, ly);
                ah[0][2] = pack_bf16(hx, hy); al[0][2] = pack_bf16(lx, ly);
                bsplit(fb2.x, hx, lx); bsplit(fb2.y, hy, ly);
                ah[0][3] = pack_bf16(hx, hy); al[0][3] = pack_bf16(lx, ly);
                bsplit(fc0.x, hx, lx); bsplit(fc0.y, hy, ly);
                ah[1][0] = pack_bf16(hx, hy); al[1][0] = pack_bf16(lx, ly);
                bsplit(fd0.x, hx, lx); bsplit(fd0.y, hy, ly);
                ah[1][1] = pack_bf16(hx, hy); al[1][1] = pack_bf16(lx, ly);
                bsplit(fc2.x, hx, lx); bsplit(fc2.y, hy, ly);
                ah[1][2] = pack_bf16(hx, hy); al[1][2] = pack_bf16(lx, ly);
                bsplit(fd2.x, hx, lx); bsplit(fd2.y, hy, ly);
                ah[1][3] = pack_bf16(hx, hy); al[1][3] = pack_bf16(lx, ly);
            }

#pragma unroll
            for (int nt = 0; nt < 8; nt++) {
                const int nb = (nt * 8 + g) * BSTRIDE + kp0 + t;
                uint32_t bh0 = Bh[nb],     bl0 = Bl[nb];
                uint32_t bh1 = Bh[nb + 4], bl1 = Bl[nb + 4];
#pragma unroll
                for (int mt = 0; mt < 2; mt++) {
                    mma_bf16(acc[mt][nt], ah[mt][0], ah[mt][1], ah[mt][2], ah[mt][3], bh0, bh1);
                    mma_bf16(acc[mt][nt], ah[mt][0], ah[mt][1], ah[mt][2], ah[mt][3], bl0, bl1);
                    mma_bf16(acc[mt][nt], al[mt][0], al[mt][1], al[mt][2], al[mt][3], bh0, bh1);
                }
            }
        }
    }

    // ---- epilogue: store Xp + fused s0/s1 ----
    // c0=(rowA, 2t), c1=(rowA, 2t+1), c2=(rowB, 2t), c3=(rowB, 2t+1)
    float p0[2][2] = {{0.f, 0.f}, {0.f, 0.f}};   // [mt][A/B] partial for s0
    float p1[2][2] = {{0.f, 0.f}, {0.f, 0.f}};
#pragma unroll
    for (int nt = 0; nt < 8; nt++) {
        float2 c0 = *(const float2*)&va0[nt * 8 + t * 2];
        float2 c1 = *(const float2*)&va1[nt * 8 + t * 2];
#pragma unroll
        for (int mt = 0; mt < 2; mt++) {
            p0[mt][0] += acc[mt][nt][0] * c0.x + acc[mt][nt][1] * c0.y;
            p0[mt][1] += acc[mt][nt][2] * c0.x + acc[mt][nt][3] * c0.y;
            p1[mt][0] += acc[mt][nt][0] * c1.x + acc[mt][nt][1] * c1.y;
            p1[mt][1] += acc[mt][nt][2] * c1.x + acc[mt][nt][3] * c1.y;
        }
    }
    // quad-reduce over t (lanes g*4 + t)
#pragma unroll
    for (int mt = 0; mt < 2; mt++)
#pragma unroll
        for (int hb = 0; hb < 2; hb++) {
            p0[mt][hb] += __shfl_xor_sync(0xFFFFFFFFu, p0[mt][hb], 1);
            p0[mt][hb] += __shfl_xor_sync(0xFFFFFFFFu, p0[mt][hb], 2);
            p1[mt][hb] += __shfl_xor_sync(0xFFFFFFFFu, p1[mt][hb], 1);
            p1[mt][hb] += __shfl_xor_sync(0xFFFFFFFFu, p1[mt][hb], 2);
        }

#pragma unroll
    for (int mt = 0; mt < 2; mt++) {
        int rowA = m0 + mt * 16 + g;
        int rowB = rowA + 8;
#pragma unroll
        for (int nt = 0; nt < 8; nt++) {
            int col = nt * 8 + t * 2;
            if (rowA < nrows)
                *(float2*)&d_Xp[(size_t)rowA * DOUT + col] =
                    make_float2(acc[mt][nt][0], acc[mt][nt][1]);
            if (rowB < nrows)
                *(float2*)&d_Xp[(size_t)rowB * DOUT + col] =
                    make_float2(acc[mt][nt][2], acc[mt][nt][3]);
        }
        if (t == 0) {
            if (rowA < nrows) { d_s0[rowA] = p0[mt][0]; d_s1[rowA] = p1[mt][0]; }
            if (rowB < nrows) { d_s0[rowB] = p0[mt][1]; d_s1[rowB] = p1[mt][1]; }
        }
    }
}

// ---------------- 2) row_ptr from sorted row_index --------------------------
__global__ void rowptr_kernel(const int* __restrict__ ri, int nrows, int ne) {
    int r = blockIdx.x * blockDim.x + threadIdx.x;
    if (r > nrows) return;
    int lo = 0, hi = ne;
    while (lo < hi) {
        int mid = (lo + hi) >> 1;
        if (ri[mid] < r) lo = mid + 1; else hi = mid;
    }
    d_rowptr[r] = lo;
}

// ---------------- 3) SDDMM + LeakyReLU + per-block min/max -----------------
__global__ void __launch_bounds__(256) edge_kernel(const int* __restrict__ ri,
                                                   const int* __restrict__ ci,
                                                   int ne) {
    float lmin = 3.4e38f, lmax = -3.4e38f;
    int ne4 = ne >> 2;
    for (int i = blockIdx.x * blockDim.x + threadIdx.x; i < ne4;
         i += gridDim.x * blockDim.x) {
        int4 r4 = *(const int4*)&ri[(size_t)i * 4];
        int4 c4 = *(const int4*)&ci[(size_t)i * 4];
        float v0 = d_s0[r4.x] + d_s1[c4.x];
        float v1 = d_s0[r4.y] + d_s1[c4.y];
        float v2 = d_s0[r4.z] + d_s1[c4.z];
        float v3 = d_s0[r4.w] + d_s1[c4.w];
        v0 = v0 > 0.f ? v0 : ALPHA * v0;
        v1 = v1 > 0.f ? v1 : ALPHA * v1;
        v2 = v2 > 0.f ? v2 : ALPHA * v2;
        v3 = v3 > 0.f ? v3 : ALPHA * v3;
        *(float4*)&d_att[(size_t)i * 4] = make_float4(v0, v1, v2, v3);
        lmin = fminf(lmin, fminf(fminf(v0, v1), fminf(v2, v3)));
        lmax = fmaxf(lmax, fmaxf(fmaxf(v0, v1), fmaxf(v2, v3)));
    }
    int gid = blockIdx.x * blockDim.x + threadIdx.x;
    int tail0 = ne4 * 4;
    if (gid < ne - tail0) {
        int e = tail0 + gid;
        float v = d_s0[ri[e]] + d_s1[ci[e]];
        v = v > 0.f ? v : ALPHA * v;
        d_att[e] = v;
        lmin = fminf(lmin, v);
        lmax = fmaxf(lmax, v);
    }
    __shared__ float smn[256], smx[256];
    int t = threadIdx.x;
    smn[t] = lmin; smx[t] = lmax;
    __syncthreads();
#pragma unroll
    for (int s = 128; s; s >>= 1) {
        if (t < s) {
            smn[t] = fminf(smn[t], smn[t + s]);
            smx[t] = fmaxf(smx[t], smx[t + s]);
        }
        __syncthreads();
    }
    if (t == 0) {
        d_bmin[blockIdx.x] = smn[0];
        d_bmax[blockIdx.x] = smx[0];
    }
}

// ---------------- 4) finalize global min / scale ---------------------------
__global__ void minmax_kernel() {
    __shared__ float smn[MMBLOCKS], smx[MMBLOCKS];
    int t = threadIdx.x;
    smn[t] = d_bmin[t];
    smx[t] = d_bmax[t];
    __syncthreads();
#pragma unroll
    for (int s = MMBLOCKS / 2; s; s >>= 1) {
        if (t < s) {
            smn[t] = fminf(smn[t], smn[t + s]);
            smx[t] = fmaxf(smx[t], smx[t + s]);
        }
        __syncthreads();
    }
    if (t == 0) {
        float mn = smn[0], mx = smx[0];
        d_mn = mn;
        d_scale = 1.0f / (mx - mn);
    }
}

// ---------------- 5) SpMM + exp + row normalization (warp per row) ---------
__global__ void __launch_bounds__(256) spmm_kernel(const int* __restrict__ ci,
                                                   float* __restrict__ out,
                                                   int nrows) {
    int gid  = blockIdx.x * blockDim.x + threadIdx.x;
    int r    = gid >> 5;
    int lane = gid & 31;
    if (r >= nrows) return;

    const float mn = d_mn, sc = d_scale;
    int e   = d_rowptr[r];
    int end = d_rowptr[r + 1];
    const int off = lane * 2;

    float ax = 0.f, ay = 0.f, s = 0.f;
    for (; e + 1 < end; e += 2) {
        int   c0 = ci[e],    c1 = ci[e + 1];
        float a0 = __expf((d_att[e]     - mn) * sc);
        float a1 = __expf((d_att[e + 1] - mn) * sc);
        float2 x0 = *(const float2*)&d_Xp[(size_t)c0 * DOUT + off];
        float2 x1 = *(const float2*)&d_Xp[(size_t)c1 * DOUT + off];
        s  += a0 + a1;
        ax += a0 * x0.x + a1 * x1.x;
        ay += a0 * x0.y + a1 * x1.y;
    }
    if (e < end) {
        int   c0 = ci[e];
        float a0 = __expf((d_att[e] - mn) * sc);
        float2 x0 = *(const float2*)&d_Xp[(size_t)c0 * DOUT + off];
        s  += a0;
        ax += a0 * x0.x;
        ay += a0 * x0.y;
    }
    float inv = 1.0f / fmaxf(s, 1e-12f);
    *(float2*)&out[(size_t)r * DOUT + off] = make_float2(ax * inv, ay * inv);
}

// ---------------- launch ---------------------------------------------------
extern "C" void kernel_launch(void* const* d_in, const int* in_sizes, int n_in,
                              void* d_out, int out_size) {
    const float* X  = (const float*)d_in[0];
    const float* W  = (const float*)d_in[1];
    const float* a0 = (const float*)d_in[2];
    const float* a1 = (const float*)d_in[3];
    const int*   ri = (const int*)d_in[4];
    const int*   ci = (const int*)d_in[5];
    float*       out = (float*)d_out;

    const int n = out_size / DOUT;   // 100000
    const int e = in_sizes[4];       // 1600000

    rowptr_kernel<<<(n + 1 + 255) / 256, 256>>>(ri, n, e);
    gemm_mma_kernel<<<(n + 255) / 256, 256>>>(X, W, a0, a1, n);
    edge_kernel<<<MMBLOCKS, 256>>>(ri, ci, e);
    minmax_kernel<<<1, MMBLOCKS>>>();
    spmm_kernel<<<(n * 32 + 255) / 256, 256>>>(ci, out, n);
}

// round 6
// speedup vs baseline: 1.5431x; 1.0289x over previous
#include <cuda_runtime.h>
#include <cuda_bf16.h>
#include <cuda_fp16.h>
#include <cstdint>

#define NN     100000
#define EE     1600000
#define DIN    256
#define DOUT   64
#define ALPHA  0.2f

// ---------------- scratch ---------------------------------------------------
__device__ __half2 d_Xp16[(size_t)NN * 32];    // 12.8 MB  X @ W  (fp16, col pairs)
__device__ float d_s0[NN];
__device__ float d_s1[NN];
__device__ float d_att[EE];                    // leakyrelu'd scores (pre-exp)
__device__ int   d_rowptr[NN + 1];
__device__ unsigned int d_gminkey;             // monotone-encoded float min
__device__ unsigned int d_gmaxkey;

// ---------------- monotone float<->uint encode ------------------------------
__device__ __forceinline__ unsigned int fenc(float f) {
    unsigned int u = __float_as_uint(f);
    return u ^ ((unsigned int)((int)u >> 31) | 0x80000000u);
}
__device__ __forceinline__ float fdec(unsigned int k) {
    unsigned int u = k ^ ((unsigned int)((int)(~k) >> 31) | 0x80000000u);
    return __uint_as_float(u);
}

// ---------------- bf16 helpers ----------------------------------------------
__device__ __forceinline__ uint32_t pack_bf16(float a, float b) {
    __nv_bfloat162 h = __floats2bfloat162_rn(a, b);   // a -> low half
    return *(uint32_t*)&h;
}
__device__ __forceinline__ void bsplit(float v, float& h, float& l) {
    h = __bfloat162float(__float2bfloat16_rn(v));
    l = v - h;
}

// mma.sync m16n8k16 bf16: D += A * B (A row-major 16x16, B col-major 16x8)
__device__ __forceinline__ void mma_bf16(float* d,
                                         uint32_t a0, uint32_t a1,
                                         uint32_t a2, uint32_t a3,
                                         uint32_t b0, uint32_t b1) {
    asm volatile(
        "mma.sync.aligned.m16n8k16.row.col.f32.bf16.bf16.f32 "
        "{%0,%1,%2,%3}, {%4,%5,%6,%7}, {%8,%9}, {%0,%1,%2,%3};"
        : "+f"(d[0]), "+f"(d[1]), "+f"(d[2]), "+f"(d[3])
        : "r"(a0), "r"(a1), "r"(a2), "r"(a3), "r"(b0), "r"(b1));
}

// ---------------- 1) bf16-split tensor GEMM + fused scores ------------------
#define KC        64
#define BSTRIDE   36

__global__ void __launch_bounds__(256, 2)
gemm_mma_kernel(const float* __restrict__ X, const float* __restrict__ W,
                const float* __restrict__ va0, const float* __restrict__ va1,
                int nrows) {
    __shared__ uint32_t Bh[DOUT * BSTRIDE];
    __shared__ uint32_t Bl[DOUT * BSTRIDE];

    const int tid  = threadIdx.x;
    const int wid  = tid >> 5;
    const int lane = tid & 31;
    const int g    = lane >> 2;
    const int t    = lane & 3;

    const int m0 = blockIdx.x * 256 + wid * 32;
    const int r0 = m0 + g, r1 = m0 + g + 8, r2 = m0 + g + 16, r3 = m0 + g + 24;
    const bool v0 = r0 < nrows, v1 = r1 < nrows, v2 = r2 < nrows, v3 = r3 < nrows;
    const float* x0 = X + (size_t)r0 * DIN;
    const float* x1 = X + (size_t)r1 * DIN;
    const float* x2 = X + (size_t)r2 * DIN;
    const float* x3 = X + (size_t)r3 * DIN;

    float acc[2][8][4];
#pragma unroll
    for (int mt = 0; mt < 2; mt++)
#pragma unroll
        for (int nt = 0; nt < 8; nt++)
#pragma unroll
            for (int q = 0; q < 4; q++) acc[mt][nt][q] = 0.f;

#pragma unroll 1
    for (int kc = 0; kc < DIN / KC; kc++) {
        if (kc) __syncthreads();
        for (int idx = tid; idx < DOUT * (KC / 2); idx += 256) {
            int n  = idx & 63;
            int kp = idx >> 6;
            int k  = kc * KC + kp * 2;
            float w0 = W[(size_t)k * DOUT + n];
            float w1 = W[(size_t)(k + 1) * DOUT + n];
            float h0, l0, h1, l1;
            bsplit(w0, h0, l0);
            bsplit(w1, h1, l1);
            Bh[n * BSTRIDE + kp] = pack_bf16(h0, h1);
            Bl[n * BSTRIDE + kp] = pack_bf16(l0, l1);
        }
        __syncthreads();

#pragma unroll
        for (int s = 0; s < KC / 16; s++) {
            const int ks  = kc * KC + s * 16;
            const int kp0 = s * 8;

            float2 fa0 = v0 ? *(const float2*)(x0 + ks + 2 * t)     : make_float2(0.f, 0.f);
            float2 fa2 = v0 ? *(const float2*)(x0 + ks + 2 * t + 8) : make_float2(0.f, 0.f);
            float2 fb0 = v1 ? *(const float2*)(x1 + ks + 2 * t)     : make_float2(0.f, 0.f);
            float2 fb2 = v1 ? *(const float2*)(x1 + ks + 2 * t + 8) : make_float2(0.f, 0.f);
            float2 fc0 = v2 ? *(const float2*)(x2 + ks + 2 * t)     : make_float2(0.f, 0.f);
            float2 fc2 = v2 ? *(const float2*)(x2 + ks + 2 * t + 8) : make_float2(0.f, 0.f);
            float2 fd0 = v3 ? *(const float2*)(x3 + ks + 2 * t)     : make_float2(0.f, 0.f);
            float2 fd2 = v3 ? *(const float2*)(x3 + ks + 2 * t + 8) : make_float2(0.f, 0.f);

            uint32_t ah[2][4], al[2][4];
            {
                float hx, lx, hy, ly;
                bsplit(fa0.x, hx, lx); bsplit(fa0.y, hy, ly);
                ah[0][0] = pack_bf16(hx, hy); al[0][0] = pack_bf16(lx, ly);
                bsplit(fb0.x, hx, lx); bsplit(fb0.y, hy, ly);
                ah[0][1] = pack_bf16(hx, hy); al[0][1] = pack_bf16(lx, ly);
                bsplit(fa2.x, hx, lx); bsplit(fa2.y, hy, ly);
                ah[0][2] = pack_bf16(hx, hy); al[0][2] = pack_bf16(lx, ly);
                bsplit(fb2.x, hx, lx); bsplit(fb2.y, hy, ly);
                ah[0][3] = pack_bf16(hx, hy); al[0][3] = pack_bf16(lx, ly);
                bsplit(fc0.x, hx, lx); bsplit(fc0.y, hy, ly);
                ah[1][0] = pack_bf16(hx, hy); al[1][0] = pack_bf16(lx, ly);
                bsplit(fd0.x, hx, lx); bsplit(fd0.y, hy, ly);
                ah[1][1] = pack_bf16(hx, hy); al[1][1] = pack_bf16(lx, ly);
                bsplit(fc2.x, hx, lx); bsplit(fc2.y, hy, ly);
                ah[1][2] = pack_bf16(hx, hy); al[1][2] = pack_bf16(lx, ly);
                bsplit(fd2.x, hx, lx); bsplit(fd2.y, hy, ly);
                ah[1][3] = pack_bf16(hx, hy); al[1][3] = pack_bf16(lx, ly);
            }

#pragma unroll
            for (int nt = 0; nt < 8; nt++) {
                const int nb = (nt * 8 + g) * BSTRIDE + kp0 + t;
                uint32_t bh0 = Bh[nb],     bl0 = Bl[nb];
                uint32_t bh1 = Bh[nb + 4], bl1 = Bl[nb + 4];
#pragma unroll
                for (int mt = 0; mt < 2; mt++) {
                    mma_bf16(acc[mt][nt], ah[mt][0], ah[mt][1], ah[mt][2], ah[mt][3], bh0, bh1);
                    mma_bf16(acc[mt][nt], ah[mt][0], ah[mt][1], ah[mt][2], ah[mt][3], bl0, bl1);
                    mma_bf16(acc[mt][nt], al[mt][0], al[mt][1], al[mt][2], al[mt][3], bh0, bh1);
                }
            }
        }
    }

    // ---- epilogue: fp16 Xp store + fused s0/s1 ----
    float p0[2][2] = {{0.f, 0.f}, {0.f, 0.f}};
    float p1[2][2] = {{0.f, 0.f}, {0.f, 0.f}};
#pragma unroll
    for (int nt = 0; nt < 8; nt++) {
        float2 c0 = *(const float2*)&va0[nt * 8 + t * 2];
        float2 c1 = *(const float2*)&va1[nt * 8 + t * 2];
#pragma unroll
        for (int mt = 0; mt < 2; mt++) {
            p0[mt][0] += acc[mt][nt][0] * c0.x + acc[mt][nt][1] * c0.y;
            p0[mt][1] += acc[mt][nt][2] * c0.x + acc[mt][nt][3] * c0.y;
            p1[mt][0] += acc[mt][nt][0] * c1.x + acc[mt][nt][1] * c1.y;
            p1[mt][1] += acc[mt][nt][2] * c1.x + acc[mt][nt][3] * c1.y;
        }
    }
#pragma unroll
    for (int mt = 0; mt < 2; mt++)
#pragma unroll
        for (int hb = 0; hb < 2; hb++) {
            p0[mt][hb] += __shfl_xor_sync(0xFFFFFFFFu, p0[mt][hb], 1);
            p0[mt][hb] += __shfl_xor_sync(0xFFFFFFFFu, p0[mt][hb], 2);
            p1[mt][hb] += __shfl_xor_sync(0xFFFFFFFFu, p1[mt][hb], 1);
            p1[mt][hb] += __shfl_xor_sync(0xFFFFFFFFu, p1[mt][hb], 2);
        }

#pragma unroll
    for (int mt = 0; mt < 2; mt++) {
        int rowA = m0 + mt * 16 + g;
        int rowB = rowA + 8;
#pragma unroll
        for (int nt = 0; nt < 8; nt++) {
            int cp = nt * 4 + t;     // col-pair index (cols 2cp, 2cp+1)
            if (rowA < nrows)
                d_Xp16[(size_t)rowA * 32 + cp] =
                    __floats2half2_rn(acc[mt][nt][0], acc[mt][nt][1]);
            if (rowB < nrows)
                d_Xp16[(size_t)rowB * 32 + cp] =
                    __floats2half2_rn(acc[mt][nt][2], acc[mt][nt][3]);
        }
        if (t == 0) {
            if (rowA < nrows) { d_s0[rowA] = p0[mt][0]; d_s1[rowA] = p1[mt][0]; }
            if (rowB < nrows) { d_s0[rowB] = p0[mt][1]; d_s1[rowB] = p1[mt][1]; }
        }
    }
}

// ---------------- 2) row_ptr from sorted row_index + key init ---------------
__global__ void rowptr_kernel(const int* __restrict__ ri, int nrows, int ne) {
    if (blockIdx.x == 0 && threadIdx.x == 0) {
        d_gminkey = 0xFFFFFFFFu;
        d_gmaxkey = 0u;
    }
    int r = blockIdx.x * blockDim.x + threadIdx.x;
    if (r > nrows) return;
    int lo = 0, hi = ne;
    while (lo < hi) {
        int mid = (lo + hi) >> 1;
        if (ri[mid] < r) lo = mid + 1; else hi = mid;
    }
    d_rowptr[r] = lo;
}

// ---------------- 3) SDDMM + LeakyReLU + atomic global min/max --------------
// one int4 (4 edges) per thread, exact grid, warp-shuffle reduce, RED atomics
__global__ void __launch_bounds__(256) edge_kernel(const int* __restrict__ ri,
                                                   const int* __restrict__ ci,
                                                   int ne) {
    const int ne4  = ne >> 2;
    const int tail = ne - ne4 * 4;
    const int i    = blockIdx.x * blockDim.x + threadIdx.x;

    float lmin = 3.4e38f, lmax = -3.4e38f;
    if (i < ne4) {
        int4 r4 = *(const int4*)&ri[(size_t)i * 4];
        int4 c4 = *(const int4*)&ci[(size_t)i * 4];
        float v0 = d_s0[r4.x] + d_s1[c4.x];
        float v1 = d_s0[r4.y] + d_s1[c4.y];
        float v2 = d_s0[r4.z] + d_s1[c4.z];
        float v3 = d_s0[r4.w] + d_s1[c4.w];
        v0 = v0 > 0.f ? v0 : ALPHA * v0;
        v1 = v1 > 0.f ? v1 : ALPHA * v1;
        v2 = v2 > 0.f ? v2 : ALPHA * v2;
        v3 = v3 > 0.f ? v3 : ALPHA * v3;
        *(float4*)&d_att[(size_t)i * 4] = make_float4(v0, v1, v2, v3);
        lmin = fminf(fminf(v0, v1), fminf(v2, v3));
        lmax = fmaxf(fmaxf(v0, v1), fmaxf(v2, v3));
    } else if (i - ne4 < tail) {
        int e = ne4 * 4 + (i - ne4);
        float v = d_s0[ri[e]] + d_s1[ci[e]];
        v = v > 0.f ? v : ALPHA * v;
        d_att[e] = v;
        lmin = v; lmax = v;
    }
#pragma unroll
    for (int o = 16; o; o >>= 1) {
        lmin = fminf(lmin, __shfl_xor_sync(0xFFFFFFFFu, lmin, o));
        lmax = fmaxf(lmax, __shfl_xor_sync(0xFFFFFFFFu, lmax, o));
    }
    if ((threadIdx.x & 31) == 0) {
        atomicMin(&d_gminkey, fenc(lmin));
        atomicMax(&d_gmaxkey, fenc(lmax));
    }
}

// ---------------- 4) SpMM + exp + row normalization (warp per row) ----------
__global__ void __launch_bounds__(256) spmm_kernel(const int* __restrict__ ci,
                                                   float* __restrict__ out,
                                                   int nrows) {
    int gid  = blockIdx.x * blockDim.x + threadIdx.x;
    int r    = gid >> 5;
    int lane = gid & 31;
    if (r >= nrows) return;

    const float mn = fdec(d_gminkey);
    const float sc = 1.0f / (fdec(d_gmaxkey) - mn);
    int e   = d_rowptr[r];
    int end = d_rowptr[r + 1];

    const __half2* xp = d_Xp16 + lane;
    float ax = 0.f, ay = 0.f, s = 0.f;
    for (; e + 3 < end; e += 4) {
        float a0 = __expf((d_att[e]     - mn) * sc);
        float a1 = __expf((d_att[e + 1] - mn) * sc);
        float a2 = __expf((d_att[e + 2] - mn) * sc);
        float a3 = __expf((d_att[e + 3] - mn) * sc);
        float2 x0 = __half22float2(xp[(size_t)ci[e]     * 32]);
        float2 x1 = __half22float2(xp[(size_t)ci[e + 1] * 32]);
        float2 x2 = __half22float2(xp[(size_t)ci[e + 2] * 32]);
        float2 x3 = __half22float2(xp[(size_t)ci[e + 3] * 32]);
        s  += (a0 + a1) + (a2 + a3);
        ax += a0 * x0.x + a1 * x1.x + a2 * x2.x + a3 * x3.x;
        ay += a0 * x0.y + a1 * x1.y + a2 * x2.y + a3 * x3.y;
    }
    for (; e < end; e++) {
        float a0 = __expf((d_att[e] - mn) * sc);
        float2 x0 = __half22float2(xp[(size_t)ci[e] * 32]);
        s  += a0;
        ax += a0 * x0.x;
        ay += a0 * x0.y;
    }
    float inv = 1.0f / fmaxf(s, 1e-12f);
    *(float2*)&out[(size_t)r * DOUT + lane * 2] = make_float2(ax * inv, ay * inv);
}

// ---------------- launch ---------------------------------------------------
extern "C" void kernel_launch(void* const* d_in, const int* in_sizes, int n_in,
                              void* d_out, int out_size) {
    const float* X  = (const float*)d_in[0];
    const float* W  = (const float*)d_in[1];
    const float* a0 = (const float*)d_in[2];
    const float* a1 = (const float*)d_in[3];
    const int*   ri = (const int*)d_in[4];
    const int*   ci = (const int*)d_in[5];
    float*       out = (float*)d_out;

    const int n = out_size / DOUT;   // 100000
    const int e = in_sizes[4];       // 1600000

    rowptr_kernel<<<(n + 1 + 255) / 256, 256>>>(ri, n, e);
    gemm_mma_kernel<<<(n + 255) / 256, 256>>>(X, W, a0, a1, n);
    const int ne4 = e >> 2, tail = e - ne4 * 4;
    edge_kernel<<<(ne4 + tail + 255) / 256, 256>>>(ri, ci, e);
    spmm_kernel<<<(n * 32 + 255) / 256, 256>>>(ci, out, n);
}

// round 7
// speedup vs baseline: 1.7140x; 1.1108x over previous
#include <cuda_runtime.h>
#include <cuda_fp16.h>
#include <cstdint>

#define NN     100000
#define EE     1600000
#define DIN    256
#define DOUT   64
#define ALPHA  0.2f

// ---------------- scratch ---------------------------------------------------
__device__ __half2 d_Xp16[(size_t)NN * 32];    // 12.8 MB  X @ W  (fp16 col pairs)
__device__ float d_s0[NN];
__device__ float d_s1[NN];
__device__ float d_att[EE];                    // leakyrelu'd scores (pre-exp)
__device__ int   d_rowptr[NN + 1];
__device__ unsigned int d_gminkey;             // monotone-encoded float min
__device__ unsigned int d_gmaxkey;

// ---------------- monotone float<->uint encode ------------------------------
__device__ __forceinline__ unsigned int fenc(float f) {
    unsigned int u = __float_as_uint(f);
    return u ^ ((unsigned int)((int)u >> 31) | 0x80000000u);
}
__device__ __forceinline__ float fdec(unsigned int k) {
    unsigned int u = k ^ ((unsigned int)((int)(~k) >> 31) | 0x80000000u);
    return __uint_as_float(u);
}

// ---------------- fp16 helpers ----------------------------------------------
__device__ __forceinline__ uint32_t packh2(float a, float b) {
    __half2 h = __floats2half2_rn(a, b);      // a -> low half
    return *(uint32_t*)&h;
}

// mma.sync m16n8k16 fp16: D += A * B (A row-major 16x16, B col-major 16x8)
__device__ __forceinline__ void mma_fp16(float* d,
                                         uint32_t a0, uint32_t a1,
                                         uint32_t a2, uint32_t a3,
                                         uint32_t b0, uint32_t b1) {
    asm volatile(
        "mma.sync.aligned.m16n8k16.row.col.f32.f16.f16.f32 "
        "{%0,%1,%2,%3}, {%4,%5,%6,%7}, {%8,%9}, {%0,%1,%2,%3};"
        : "+f"(d[0]), "+f"(d[1]), "+f"(d[2]), "+f"(d[3])
        : "r"(a0), "r"(a1), "r"(a2), "r"(a3), "r"(b0), "r"(b1));
}

// ---------------- 1) fp16 2-pass tensor GEMM + fused scores -----------------
// CTA: 256 threads / 8 warps / 256 rows. Warp w: rows [w*32,w*32+32), 64 cols.
// B (all of K) in smem once, fp16x2, stride 132 words: bank = 4g+t+kp0,
// bijective over warp -> conflict-free LDS. A: hi=fp16(v), lo=fp16(v-hi);
// passes hi*B + lo*B  => A exact to 2^-22, B rounding ~1.4e-4 RMS.
#define BST2 132   // uint32 words per n-col (128 kpairs + 4 pad)

__global__ void __launch_bounds__(256, 2)
gemm_mma_kernel(const float* __restrict__ X, const float* __restrict__ W,
                const float* __restrict__ va0, const float* __restrict__ va1,
                int nrows) {
    __shared__ uint32_t Bs[DOUT * BST2];      // 33.8 KB  W^T fp16x2, full K

    const int tid  = threadIdx.x;
    const int wid  = tid >> 5;
    const int lane = tid & 31;
    const int g    = lane >> 2;
    const int t    = lane & 3;

    // fill B once: 64 n-cols x 128 kpairs (coalesced gmem reads)
    for (int idx = tid; idx < DOUT * (DIN / 2); idx += 256) {
        int n  = idx & 63;
        int kp = idx >> 6;
        int k  = kp * 2;
        Bs[n * BST2 + kp] = packh2(W[(size_t)k * DOUT + n],
                                   W[(size_t)(k + 1) * DOUT + n]);
    }

    const int m0 = blockIdx.x * 256 + wid * 32;
    const int r0 = m0 + g, r1 = m0 + g + 8, r2 = m0 + g + 16, r3 = m0 + g + 24;
    const bool v0 = r0 < nrows, v1 = r1 < nrows, v2 = r2 < nrows, v3 = r3 < nrows;
    const float* x0 = X + (size_t)r0 * DIN;
    const float* x1 = X + (size_t)r1 * DIN;
    const float* x2 = X + (size_t)r2 * DIN;
    const float* x3 = X + (size_t)r3 * DIN;

    float acc[2][8][4];
#pragma unroll
    for (int mt = 0; mt < 2; mt++)
#pragma unroll
        for (int nt = 0; nt < 8; nt++)
#pragma unroll
            for (int q = 0; q < 4; q++) acc[mt][nt][q] = 0.f;

    // A fragment loader for one 16-k step into an 8-float2 buffer
    auto loadA = [&](float2* d, int s) {
        const int ks = s * 16;
        d[0] = v0 ? *(const float2*)(x0 + ks + 2 * t)     : make_float2(0.f, 0.f);
        d[1] = v1 ? *(const float2*)(x1 + ks + 2 * t)     : make_float2(0.f, 0.f);
        d[2] = v0 ? *(const float2*)(x0 + ks + 2 * t + 8) : make_float2(0.f, 0.f);
        d[3] = v1 ? *(const float2*)(x1 + ks + 2 * t + 8) : make_float2(0.f, 0.f);
        d[4] = v2 ? *(const float2*)(x2 + ks + 2 * t)     : make_float2(0.f, 0.f);
        d[5] = v3 ? *(const float2*)(x3 + ks + 2 * t)     : make_float2(0.f, 0.f);
        d[6] = v2 ? *(const float2*)(x2 + ks + 2 * t + 8) : make_float2(0.f, 0.f);
        d[7] = v3 ? *(const float2*)(x3 + ks + 2 * t + 8) : make_float2(0.f, 0.f);
    };
    // convert + 16 k-step worth of mmas from a buffer
    auto compute = [&](const float2* d, int s) {
        uint32_t ah[2][4], al[2][4];
#pragma unroll
        for (int i = 0; i < 8; i++) {
            uint32_t hi = packh2(d[i].x, d[i].y);
            __half2  h2 = *(const __half2*)&hi;
            float2   hb = __half22float2(h2);
            uint32_t lo = packh2(d[i].x - hb.x, d[i].y - hb.y);
            ah[i >> 2][i & 3] = hi;
            al[i >> 2][i & 3] = lo;
        }
        const int kp0 = s * 8;
#pragma unroll
        for (int nt = 0; nt < 8; nt++) {
            const int nb = (nt * 8 + g) * BST2 + kp0 + t;
            uint32_t b0 = Bs[nb], b1 = Bs[nb + 4];
#pragma unroll
            for (int mt = 0; mt < 2; mt++) {
                mma_fp16(acc[mt][nt], ah[mt][0], ah[mt][1], ah[mt][2], ah[mt][3], b0, b1);
                mma_fp16(acc[mt][nt], al[mt][0], al[mt][1], al[mt][2], al[mt][3], b0, b1);
            }
        }
    };

    float2 bufA[8], bufB[8];
    loadA(bufA, 0);
    __syncthreads();          // B smem ready (also after A prefetch issued)

#pragma unroll 1
    for (int s = 0; s < 16; s += 2) {
        if (s + 1 < 16) loadA(bufB, s + 1);
        compute(bufA, s);
        if (s + 2 < 16) loadA(bufA, s + 2);
        if (s + 1 < 16) compute(bufB, s + 1);
    }

    // ---- epilogue: fp16 Xp store + fused s0/s1 ----
    float p0[2][2] = {{0.f, 0.f}, {0.f, 0.f}};
    float p1[2][2] = {{0.f, 0.f}, {0.f, 0.f}};
#pragma unroll
    for (int nt = 0; nt < 8; nt++) {
        float2 c0 = *(const float2*)&va0[nt * 8 + t * 2];
        float2 c1 = *(const float2*)&va1[nt * 8 + t * 2];
#pragma unroll
        for (int mt = 0; mt < 2; mt++) {
            p0[mt][0] += acc[mt][nt][0] * c0.x + acc[mt][nt][1] * c0.y;
            p0[mt][1] += acc[mt][nt][2] * c0.x + acc[mt][nt][3] * c0.y;
            p1[mt][0] += acc[mt][nt][0] * c1.x + acc[mt][nt][1] * c1.y;
            p1[mt][1] += acc[mt][nt][2] * c1.x + acc[mt][nt][3] * c1.y;
        }
    }
#pragma unroll
    for (int mt = 0; mt < 2; mt++)
#pragma unroll
        for (int hb = 0; hb < 2; hb++) {
            p0[mt][hb] += __shfl_xor_sync(0xFFFFFFFFu, p0[mt][hb], 1);
            p0[mt][hb] += __shfl_xor_sync(0xFFFFFFFFu, p0[mt][hb], 2);
            p1[mt][hb] += __shfl_xor_sync(0xFFFFFFFFu, p1[mt][hb], 1);
            p1[mt][hb] += __shfl_xor_sync(0xFFFFFFFFu, p1[mt][hb], 2);
        }

#pragma unroll
    for (int mt = 0; mt < 2; mt++) {
        int rowA = m0 + mt * 16 + g;
        int rowB = rowA + 8;
#pragma unroll
        for (int nt = 0; nt < 8; nt++) {
            int cp = nt * 4 + t;     // col-pair index (cols 2cp, 2cp+1)
            if (rowA < nrows)
                d_Xp16[(size_t)rowA * 32 + cp] =
                    __floats2half2_rn(acc[mt][nt][0], acc[mt][nt][1]);
            if (rowB < nrows)
                d_Xp16[(size_t)rowB * 32 + cp] =
                    __floats2half2_rn(acc[mt][nt][2], acc[mt][nt][3]);
        }
        if (t == 0) {
            if (rowA < nrows) { d_s0[rowA] = p0[mt][0]; d_s1[rowA] = p1[mt][0]; }
            if (rowB < nrows) { d_s0[rowB] = p0[mt][1]; d_s1[rowB] = p1[mt][1]; }
        }
    }
}

// ---------------- 2) row_ptr from sorted row_index + key init ---------------
__global__ void rowptr_kernel(const int* __restrict__ ri, int nrows, int ne) {
    if (blockIdx.x == 0 && threadIdx.x == 0) {
        d_gminkey = 0xFFFFFFFFu;
        d_gmaxkey = 0u;
    }
    int r = blockIdx.x * blockDim.x + threadIdx.x;
    if (r > nrows) return;
    int lo = 0, hi = ne;
    while (lo < hi) {
        int mid = (lo + hi) >> 1;
        if (ri[mid] < r) lo = mid + 1; else hi = mid;
    }
    d_rowptr[r] = lo;
}

// ---------------- 3) SDDMM + LeakyReLU + atomic global min/max --------------
__global__ void __launch_bounds__(256) edge_kernel(const int* __restrict__ ri,
                                                   const int* __restrict__ ci,
                                                   int ne) {
    const int ne4  = ne >> 2;
    const int tail = ne - ne4 * 4;
    const int i    = blockIdx.x * blockDim.x + threadIdx.x;

    float lmin = 3.4e38f, lmax = -3.4e38f;
    if (i < ne4) {
        int4 r4 = *(const int4*)&ri[(size_t)i * 4];
        int4 c4 = *(const int4*)&ci[(size_t)i * 4];
        float v0 = d_s0[r4.x] + d_s1[c4.x];
        float v1 = d_s0[r4.y] + d_s1[c4.y];
        float v2 = d_s0[r4.z] + d_s1[c4.z];
        float v3 = d_s0[r4.w] + d_s1[c4.w];
        v0 = v0 > 0.f ? v0 : ALPHA * v0;
        v1 = v1 > 0.f ? v1 : ALPHA * v1;
        v2 = v2 > 0.f ? v2 : ALPHA * v2;
        v3 = v3 > 0.f ? v3 : ALPHA * v3;
        *(float4*)&d_att[(size_t)i * 4] = make_float4(v0, v1, v2, v3);
        lmin = fminf(fminf(v0, v1), fminf(v2, v3));
        lmax = fmaxf(fmaxf(v0, v1), fmaxf(v2, v3));
    } else if (i - ne4 < tail) {
        int e = ne4 * 4 + (i - ne4);
        float v = d_s0[ri[e]] + d_s1[ci[e]];
        v = v > 0.f ? v : ALPHA * v;
        d_att[e] = v;
        lmin = v; lmax = v;
    }
#pragma unroll
    for (int o = 16; o; o >>= 1) {
        lmin = fminf(lmin, __shfl_xor_sync(0xFFFFFFFFu, lmin, o));
        lmax = fmaxf(lmax, __shfl_xor_sync(0xFFFFFFFFu, lmax, o));
    }
    if ((threadIdx.x & 31) == 0) {
        atomicMin(&d_gminkey, fenc(lmin));
        atomicMax(&d_gmaxkey, fenc(lmax));
    }
}

// ---------------- 4) SpMM: lane-parallel exp + shfl broadcast ---------------
// Warp per row. Lanes batch-compute exp(att)/ci for 32 edges, then inner loop
// broadcasts (a, c) via shfl.idx; each lane accumulates its 2 columns.
__global__ void __launch_bounds__(256) spmm_kernel(const int* __restrict__ ci,
                                                   float* __restrict__ out,
                                                   int nrows) {
    int gid  = blockIdx.x * blockDim.x + threadIdx.x;
    int r    = gid >> 5;
    int lane = gid & 31;
    if (r >= nrows) return;

    const float mn = fdec(d_gminkey);
    const float sc = 1.0f / (fdec(d_gmaxkey) - mn);
    const int e0  = d_rowptr[r];
    const int end = d_rowptr[r + 1];

    const __half2* xp = d_Xp16 + lane;
    float ax = 0.f, ay = 0.f, s = 0.f;

    for (int b = e0; b < end; b += 32) {
        const int n = min(32, end - b);
        float a = 0.f;
        int   c = 0;
        if (lane < n) {
            a = __expf((d_att[b + lane] - mn) * sc);
            c = ci[b + lane];
        }
        s += a;

        int j = 0;
        for (; j + 3 < n; j += 4) {
            float a0 = __shfl_sync(0xFFFFFFFFu, a, j);
            int   c0 = __shfl_sync(0xFFFFFFFFu, c, j);
            float a1 = __shfl_sync(0xFFFFFFFFu, a, j + 1);
            int   c1 = __shfl_sync(0xFFFFFFFFu, c, j + 1);
            float a2 = __shfl_sync(0xFFFFFFFFu, a, j + 2);
            int   c2 = __shfl_sync(0xFFFFFFFFu, c, j + 2);
            float a3 = __shfl_sync(0xFFFFFFFFu, a, j + 3);
            int   c3 = __shfl_sync(0xFFFFFFFFu, c, j + 3);
            float2 x0 = __half22float2(xp[(size_t)c0 * 32]);
            float2 x1 = __half22float2(xp[(size_t)c1 * 32]);
            float2 x2 = __half22float2(xp[(size_t)c2 * 32]);
            float2 x3 = __half22float2(xp[(size_t)c3 * 32]);
            ax += a0 * x0.x + a1 * x1.x + a2 * x2.x + a3 * x3.x;
            ay += a0 * x0.y + a1 * x1.y + a2 * x2.y + a3 * x3.y;
        }
        for (; j < n; j++) {
            float aj = __shfl_sync(0xFFFFFFFFu, a, j);
            int   cj = __shfl_sync(0xFFFFFFFFu, c, j);
            float2 x = __half22float2(xp[(size_t)cj * 32]);
            ax += aj * x.x;
            ay += aj * x.y;
        }
    }
    // row-sum reduce (once per row)
#pragma unroll
    for (int o = 16; o; o >>= 1)
        s += __shfl_xor_sync(0xFFFFFFFFu, s, o);

    float inv = 1.0f / fmaxf(s, 1e-12f);
    *(float2*)&out[(size_t)r * DOUT + lane * 2] = make_float2(ax * inv, ay * inv);
}

// ---------------- launch ---------------------------------------------------
extern "C" void kernel_launch(void* const* d_in, const int* in_sizes, int n_in,
                              void* d_out, int out_size) {
    const float* X  = (const float*)d_in[0];
    const float* W  = (const float*)d_in[1];
    const float* a0 = (const float*)d_in[2];
    const float* a1 = (const float*)d_in[3];
    const int*   ri = (const int*)d_in[4];
    const int*   ci = (const int*)d_in[5];
    float*       out = (float*)d_out;

    const int n = out_size / DOUT;   // 100000
    const int e = in_sizes[4];       // 1600000

    rowptr_kernel<<<(n + 1 + 255) / 256, 256>>>(ri, n, e);
    gemm_mma_kernel<<<(n + 255) / 256, 256>>>(X, W, a0, a1, n);
    const int ne4 = e >> 2, tail = e - ne4 * 4;
    edge_kernel<<<(ne4 + tail + 255) / 256, 256>>>(ri, ci, e);
    spmm_kernel<<<(n * 32 + 255) / 256, 256>>>(ci, out, n);
}